// round 4
// baseline (speedup 1.0000x reference)
#include <cuda_runtime.h>

// Haar pair transform: x (64, 4096, 256) f32 -> out (64, 2048, 512) f32
// Chunk-local identity mapping: each contiguous 512-float chunk transforms in place:
//   out[2f]   = (in[f] + in[f+256]) * INV_SQRT2
//   out[2f+1] = (in[f] - in[f+256]) * INV_SQRT2
//
// R4: R3's 256-bit accesses + .cs (cache-streaming, evict-first) policy on all
// loads and stores — data is strictly single-touch, so keep both the 256MB read
// stream and 256MB write stream marked evict-first in L1/L2. 512-thread blocks.

__global__ void __launch_bounds__(512) haar_kernel(
    const float* __restrict__ in,
    float* __restrict__ out,
    int nt)                           // total threads = out floats / 16
{
    int t = blockIdx.x * blockDim.x + threadIdx.x;
    if (t >= nt) return;

    const float c = 0.70710678118654752440f;

    int chunk = t >> 5;               // 32 lanes cover one 512-float chunk
    int j     = t & 31;

    const float* p0 = in + ((long)chunk << 9) + (j << 3);   // x0: 8 floats
    const float* p1 = p0 + 256;                             // x1: 8 floats

    float a0,a1,a2,a3,a4,a5,a6,a7;
    float b0,b1,b2,b3,b4,b5,b6,b7;

    asm volatile("ld.global.cs.v8.f32 {%0,%1,%2,%3,%4,%5,%6,%7}, [%8];"
        : "=f"(a0),"=f"(a1),"=f"(a2),"=f"(a3),
          "=f"(a4),"=f"(a5),"=f"(a6),"=f"(a7)
        : "l"(p0));
    asm volatile("ld.global.cs.v8.f32 {%0,%1,%2,%3,%4,%5,%6,%7}, [%8];"
        : "=f"(b0),"=f"(b1),"=f"(b2),"=f"(b3),
          "=f"(b4),"=f"(b5),"=f"(b6),"=f"(b7)
        : "l"(p1));

    float* q = out + ((long)chunk << 9) + (j << 4);         // 16 contiguous outputs

    float o0 = (a0 + b0) * c, o1 = (a0 - b0) * c;
    float o2 = (a1 + b1) * c, o3 = (a1 - b1) * c;
    float o4 = (a2 + b2) * c, o5 = (a2 - b2) * c;
    float o6 = (a3 + b3) * c, o7 = (a3 - b3) * c;

    asm volatile("st.global.cs.v8.f32 [%0], {%1,%2,%3,%4,%5,%6,%7,%8};"
        :: "l"(q),
           "f"(o0),"f"(o1),"f"(o2),"f"(o3),
           "f"(o4),"f"(o5),"f"(o6),"f"(o7)
        : "memory");

    float s0 = (a4 + b4) * c, s1 = (a4 - b4) * c;
    float s2 = (a5 + b5) * c, s3 = (a5 - b5) * c;
    float s4 = (a6 + b6) * c, s5 = (a6 - b6) * c;
    float s6 = (a7 + b7) * c, s7 = (a7 - b7) * c;

    asm volatile("st.global.cs.v8.f32 [%0], {%1,%2,%3,%4,%5,%6,%7,%8};"
        :: "l"(q + 8),
           "f"(s0),"f"(s1),"f"(s2),"f"(s3),
           "f"(s4),"f"(s5),"f"(s6),"f"(s7)
        : "memory");
}

extern "C" void kernel_launch(void* const* d_in, const int* in_sizes, int n_in,
                              void* d_out, int out_size)
{
    const float* x = (const float*)d_in[0];
    float* out = (float*)d_out;

    int nt = out_size / 16;                      // 4,194,304 threads (16 floats out each)
    int threads = 512;
    int blocks = (nt + threads - 1) / threads;   // 8,192 blocks

    haar_kernel<<<blocks, threads>>>(x, out, nt);
}

// round 5
// speedup vs baseline: 1.0008x; 1.0008x over previous
#include <cuda_runtime.h>

// Haar pair transform: x (64, 4096, 256) f32 -> out (64, 2048, 512) f32
// Chunk-local identity mapping: each contiguous 512-float chunk transforms in place:
//   out[2f]   = (in[f] + in[f+256]) * INV_SQRT2
//   out[2f+1] = (in[f] - in[f+256]) * INV_SQRT2
//
// R5: R4 (.cs 256-bit accesses) + ILP x2 over chunks: each thread covers the
// same lane j of TWO adjacent 512-float chunks, front-batching 4 independent
// LDG.E.256 (128 B/lane in flight) before any store. All accesses stay fully
// dense at warp granularity (each warp instruction spans a contiguous 1 KB).

__global__ void __launch_bounds__(256) haar_kernel(
    const float* __restrict__ in,
    float* __restrict__ out,
    int nt)                           // total threads = out floats / 32
{
    int t = blockIdx.x * blockDim.x + threadIdx.x;
    if (t >= nt) return;

    const float c = 0.70710678118654752440f;

    int u = t >> 5;                   // chunk-pair index (chunks 2u, 2u+1)
    int j = t & 31;                   // lane within chunk

    const float* base = in + ((long)u << 10) + (j << 3);

    float a0,a1,a2,a3,a4,a5,a6,a7;    // chunk0 x0
    float b0,b1,b2,b3,b4,b5,b6,b7;    // chunk0 x1
    float e0,e1,e2,e3,e4,e5,e6,e7;    // chunk1 x0
    float g0,g1,g2,g3,g4,g5,g6,g7;    // chunk1 x1

    asm volatile("ld.global.cs.v8.f32 {%0,%1,%2,%3,%4,%5,%6,%7}, [%8];"
        : "=f"(a0),"=f"(a1),"=f"(a2),"=f"(a3),"=f"(a4),"=f"(a5),"=f"(a6),"=f"(a7)
        : "l"(base));
    asm volatile("ld.global.cs.v8.f32 {%0,%1,%2,%3,%4,%5,%6,%7}, [%8];"
        : "=f"(b0),"=f"(b1),"=f"(b2),"=f"(b3),"=f"(b4),"=f"(b5),"=f"(b6),"=f"(b7)
        : "l"(base + 256));
    asm volatile("ld.global.cs.v8.f32 {%0,%1,%2,%3,%4,%5,%6,%7}, [%8];"
        : "=f"(e0),"=f"(e1),"=f"(e2),"=f"(e3),"=f"(e4),"=f"(e5),"=f"(e6),"=f"(e7)
        : "l"(base + 512));
    asm volatile("ld.global.cs.v8.f32 {%0,%1,%2,%3,%4,%5,%6,%7}, [%8];"
        : "=f"(g0),"=f"(g1),"=f"(g2),"=f"(g3),"=f"(g4),"=f"(g5),"=f"(g6),"=f"(g7)
        : "l"(base + 768));

    float* q0 = out + ((long)u << 10) + (j << 4);   // chunk0 outputs (16 contiguous)
    float* q1 = q0 + 512;                           // chunk1 outputs

    {
        float o0 = (a0 + b0) * c, o1 = (a0 - b0) * c;
        float o2 = (a1 + b1) * c, o3 = (a1 - b1) * c;
        float o4 = (a2 + b2) * c, o5 = (a2 - b2) * c;
        float o6 = (a3 + b3) * c, o7 = (a3 - b3) * c;
        asm volatile("st.global.cs.v8.f32 [%0], {%1,%2,%3,%4,%5,%6,%7,%8};"
            :: "l"(q0), "f"(o0),"f"(o1),"f"(o2),"f"(o3),"f"(o4),"f"(o5),"f"(o6),"f"(o7)
            : "memory");
    }
    {
        float o0 = (a4 + b4) * c, o1 = (a4 - b4) * c;
        float o2 = (a5 + b5) * c, o3 = (a5 - b5) * c;
        float o4 = (a6 + b6) * c, o5 = (a6 - b6) * c;
        float o6 = (a7 + b7) * c, o7 = (a7 - b7) * c;
        asm volatile("st.global.cs.v8.f32 [%0], {%1,%2,%3,%4,%5,%6,%7,%8};"
            :: "l"(q0 + 8), "f"(o0),"f"(o1),"f"(o2),"f"(o3),"f"(o4),"f"(o5),"f"(o6),"f"(o7)
            : "memory");
    }
    {
        float o0 = (e0 + g0) * c, o1 = (e0 - g0) * c;
        float o2 = (e1 + g1) * c, o3 = (e1 - g1) * c;
        float o4 = (e2 + g2) * c, o5 = (e2 - g2) * c;
        float o6 = (e3 + g3) * c, o7 = (e3 - g3) * c;
        asm volatile("st.global.cs.v8.f32 [%0], {%1,%2,%3,%4,%5,%6,%7,%8};"
            :: "l"(q1), "f"(o0),"f"(o1),"f"(o2),"f"(o3),"f"(o4),"f"(o5),"f"(o6),"f"(o7)
            : "memory");
    }
    {
        float o0 = (e4 + g4) * c, o1 = (e4 - g4) * c;
        float o2 = (e5 + g5) * c, o3 = (e5 - g5) * c;
        float o4 = (e6 + g6) * c, o5 = (e6 - g6) * c;
        float o6 = (e7 + g7) * c, o7 = (e7 - g7) * c;
        asm volatile("st.global.cs.v8.f32 [%0], {%1,%2,%3,%4,%5,%6,%7,%8};"
            :: "l"(q1 + 8), "f"(o0),"f"(o1),"f"(o2),"f"(o3),"f"(o4),"f"(o5),"f"(o6),"f"(o7)
            : "memory");
    }
}

extern "C" void kernel_launch(void* const* d_in, const int* in_sizes, int n_in,
                              void* d_out, int out_size)
{
    const float* x = (const float*)d_in[0];
    float* out = (float*)d_out;

    int nt = out_size / 32;                      // 2,097,152 threads (32 floats out each)
    int threads = 256;
    int blocks = (nt + threads - 1) / threads;   // 8,192 blocks

    haar_kernel<<<blocks, threads>>>(x, out, nt);
}

// round 6
// speedup vs baseline: 1.0016x; 1.0008x over previous
#include <cuda_runtime.h>

// Haar pair transform: x (64, 4096, 256) f32 -> out (64, 2048, 512) f32
// Chunk-local identity mapping: each contiguous 512-float chunk transforms in place:
//   out[2f]   = (in[f] + in[f+256]) * INV_SQRT2
//   out[2f+1] = (in[f] - in[f+256]) * INV_SQRT2
//
// R6: best-known shape (R4: 2x LDG.E.256 + 2x STG.E.256 per thread, regs ~30,
// occ ~70%, 512-thread blocks) with .lu (last-use) load policy — the exact
// semantic for a single-touch read stream — and .cs evict-first stores.
// R5 showed per-SM MLP is saturated (4-load version lost occupancy 1:1);
// this locks in the high-occupancy 2-load configuration.

__global__ void __launch_bounds__(512) haar_kernel(
    const float* __restrict__ in,
    float* __restrict__ out,
    int nt)                           // total threads = out floats / 16
{
    int t = blockIdx.x * blockDim.x + threadIdx.x;
    if (t >= nt) return;

    const float c = 0.70710678118654752440f;

    int chunk = t >> 5;               // 32 lanes cover one 512-float chunk
    int j     = t & 31;

    const float* p0 = in + ((long)chunk << 9) + (j << 3);   // x0: 8 floats
    const float* p1 = p0 + 256;                             // x1: 8 floats

    float a0,a1,a2,a3,a4,a5,a6,a7;
    float b0,b1,b2,b3,b4,b5,b6,b7;

    asm volatile("ld.global.lu.v8.f32 {%0,%1,%2,%3,%4,%5,%6,%7}, [%8];"
        : "=f"(a0),"=f"(a1),"=f"(a2),"=f"(a3),
          "=f"(a4),"=f"(a5),"=f"(a6),"=f"(a7)
        : "l"(p0));
    asm volatile("ld.global.lu.v8.f32 {%0,%1,%2,%3,%4,%5,%6,%7}, [%8];"
        : "=f"(b0),"=f"(b1),"=f"(b2),"=f"(b3),
          "=f"(b4),"=f"(b5),"=f"(b6),"=f"(b7)
        : "l"(p1));

    float* q = out + ((long)chunk << 9) + (j << 4);         // 16 contiguous outputs

    float o0 = (a0 + b0) * c, o1 = (a0 - b0) * c;
    float o2 = (a1 + b1) * c, o3 = (a1 - b1) * c;
    float o4 = (a2 + b2) * c, o5 = (a2 - b2) * c;
    float o6 = (a3 + b3) * c, o7 = (a3 - b3) * c;

    asm volatile("st.global.cs.v8.f32 [%0], {%1,%2,%3,%4,%5,%6,%7,%8};"
        :: "l"(q),
           "f"(o0),"f"(o1),"f"(o2),"f"(o3),
           "f"(o4),"f"(o5),"f"(o6),"f"(o7)
        : "memory");

    float s0 = (a4 + b4) * c, s1 = (a4 - b4) * c;
    float s2 = (a5 + b5) * c, s3 = (a5 - b5) * c;
    float s4 = (a6 + b6) * c, s5 = (a6 - b6) * c;
    float s6 = (a7 + b7) * c, s7 = (a7 - b7) * c;

    asm volatile("st.global.cs.v8.f32 [%0], {%1,%2,%3,%4,%5,%6,%7,%8};"
        :: "l"(q + 8),
           "f"(s0),"f"(s1),"f"(s2),"f"(s3),
           "f"(s4),"f"(s5),"f"(s6),"f"(s7)
        : "memory");
}

extern "C" void kernel_launch(void* const* d_in, const int* in_sizes, int n_in,
                              void* d_out, int out_size)
{
    const float* x = (const float*)d_in[0];
    float* out = (float*)d_out;

    int nt = out_size / 16;                      // 4,194,304 threads (16 floats out each)
    int threads = 512;
    int blocks = (nt + threads - 1) / threads;   // 8,192 blocks

    haar_kernel<<<blocks, threads>>>(x, out, nt);
}